// round 14
// baseline (speedup 1.0000x reference)
#include <cuda_runtime.h>
#include <math.h>
#include <stdint.h>

#define S_ 512
#define B_ 64
#define I_ 256
#define H_ 1024
#define BH_ 65536
#define LBH_ 196608
#define NB 120
#define BOFF 90112
#define SMEM_DYN 135168

// int8 2-plane scales
#define SW_REC 700.0f
#define SW_XH 500.0f
#define SX 18.0f
#define C1_REC (1.0f / (127.0f * SW_REC))
#define C2_REC (C1_REC / 254.0f)
#define C1_A (1.0f / (SX * SW_XH))
#define C2_A (C1_A / 254.0f)

// ---------------- static device scratch ----------------
__device__ __align__(16) float g_P[(size_t)S_ * BH_];
__device__ __align__(16) char g_Wq[(size_t)(40 * 32 + 64) * 8192]; // blocks: [hi 4K][lo 4K]
__device__ __align__(16) char g_Xq[(size_t)S_ * 8 * 4096];         // blocks: [hi 2K][lo 2K]
__device__ __align__(16) char g_hq[2 * 3 * 32 * 4096];             // parity x layer x 32 blocks
__device__ __align__(16) float g_part[2 * NB * 8192];
__device__ unsigned g_pdone[24 * 32];
__device__ unsigned g_hready[3 * 32];
__device__ unsigned g_hused[3 * 32];
__device__ unsigned g_cnt;
__device__ volatile unsigned g_gen;

__constant__ int c_inc[3]  = {24, 48, 48};
__constant__ int c_cons[3] = {48, 48, 24};

// byte offset inside a 32-K int8 plane-block, XOR-swizzled (conflict-free)
__device__ __forceinline__ uint32_t rowoff8(int r, int k) {
    return (uint32_t)(r * 32 + (((((k >> 2) ^ (r & 4))) << 2) | (k & 3)));
}

// ---------------- PTX helpers ----------------
__device__ __forceinline__ uint32_t smem_u32(const void* p) {
    uint32_t a;
    asm("{ .reg .u64 t; cvta.to.shared.u64 t, %1; cvt.u32.u64 %0, t; }" : "=r"(a) : "l"(p));
    return a;
}
__device__ __forceinline__ void cp16(uint32_t s, const void* g) {
    asm volatile("cp.async.cg.shared.global [%0], [%1], 16;" :: "r"(s), "l"(g) : "memory");
}
__device__ __forceinline__ void cp_commit() { asm volatile("cp.async.commit_group;" ::: "memory"); }
__device__ __forceinline__ void cp_wait2()  { asm volatile("cp.async.wait_group 2;" ::: "memory"); }
__device__ __forceinline__ void cp_wait0()  { asm volatile("cp.async.wait_group 0;" ::: "memory"); }

__device__ __forceinline__ void imma(int* d, uint32_t a0, uint32_t a1, uint32_t a2,
                                     uint32_t a3, uint32_t b0, uint32_t b1) {
    asm volatile(
        "mma.sync.aligned.m16n8k32.row.col.s32.s8.s8.s32 "
        "{%0,%1,%2,%3}, {%4,%5,%6,%7}, {%8,%9}, {%0,%1,%2,%3};"
        : "+r"(d[0]), "+r"(d[1]), "+r"(d[2]), "+r"(d[3])
        : "r"(a0), "r"(a1), "r"(a2), "r"(a3), "r"(b0), "r"(b1));
}

__device__ __forceinline__ void grid_sync(unsigned nb) {
    __syncthreads();
    if (threadIdx.x == 0) {
        __threadfence();
        unsigned g = g_gen;
        if (atomicAdd(&g_cnt, 1u) == nb - 1u) {
            g_cnt = 0;
            __threadfence();
            g_gen = g + 1u;
        } else {
            while (g_gen == g) { }
        }
    }
    __syncthreads();
}
__device__ __forceinline__ void spin_ge(unsigned* ctr, unsigned tgt) {
    while (*(volatile unsigned*)ctr < tgt) { }
}

// ---------------- prep kernels ----------------
__global__ void k_init() {
    int i = blockIdx.x * blockDim.x + threadIdx.x;
    uint32_t* a = (uint32_t*)g_hq;
    if (i < 98304) a[i] = 0u;
    if (i < 24 * 32) g_pdone[i] = 0u;
    if (i < 3 * 32) { g_hready[i] = 0u; g_hused[i] = 0u; }
}
__device__ __forceinline__ void q2(float v, float s, char* hi, char* lo) {
    float sv = v * s;
    int a = __float2int_rn(sv);
    a = max(-127, min(127, a));
    int b = __float2int_rn((sv - (float)a) * 254.0f);
    b = max(-127, min(127, b));
    *hi = (char)a;
    *lo = (char)b;
}
__global__ void k_prepw(const float* __restrict__ Whh, const float* __restrict__ Wl,
                        const float* __restrict__ Ul) {
    int idx = blockIdx.x * blockDim.x + threadIdx.x;
    if (idx >= 5 * 1024 * 1024) return;
    int g = idx >> 20, rem = idx & 1048575, k = rem >> 10, f = rem & 1023;
    float v;
    if (g == 0)      v = Whh[(size_t)k * H_ + f];
    else if (g == 1) v = Ul[(size_t)k * H_ + f];
    else if (g == 2) v = Wl[(size_t)k * H_ + f];
    else if (g == 3) v = Ul[(size_t)H_ * H_ + (size_t)k * H_ + f];
    else             v = Wl[(size_t)H_ * H_ + (size_t)k * H_ + f];
    size_t blk = (size_t)(g * 8 + (f >> 7)) * 32 + (k >> 5);
    uint32_t o = rowoff8(f & 127, k & 31);
    q2(v, SW_REC, g_Wq + blk * 8192 + o, g_Wq + blk * 8192 + 4096 + o);
}
__global__ void k_prepxh(const float* __restrict__ Wxh) {
    int idx = blockIdx.x * blockDim.x + threadIdx.x;
    if (idx >= 256 * 1024) return;
    int k = idx >> 10, f = idx & 1023;
    size_t blk = 1280 + (size_t)(f >> 7) * 8 + (k >> 5);
    uint32_t o = rowoff8(f & 127, k & 31);
    q2(Wxh[(size_t)k * H_ + f], SW_XH, g_Wq + blk * 8192 + o, g_Wq + blk * 8192 + 4096 + o);
}
__global__ void k_prepx(const float* __restrict__ X) {
    int idx = blockIdx.x * blockDim.x + threadIdx.x;
    if (idx >= S_ * B_ * I_) return;
    int s = idx >> 14, b = (idx >> 8) & 63, i = idx & 255;
    size_t blk = (size_t)s * 8 + (i >> 5);
    uint32_t o = rowoff8(b, i & 31);
    q2(X[idx], SX, g_Xq + blk * 4096 + o, g_Xq + blk * 4096 + 2048 + o);
}

// ---------------- int8 GEMM block: 24 IMMA per warp per K32 ----------------
__device__ __forceinline__ void sub_i8(const char* pA, const char* pB, int wid, int lane,
                                       int hh[2][4][4], int md[2][4][4]) {
    const int g = lane >> 2, t = lane & 3;
    const int fr = (wid >> 1) * 32, nb = (wid & 1) * 32;
    const int sw = g & 4;
    uint32_t ah[2][4], al[2][4], bh[4][2], bl[4][2];
#pragma unroll
    for (int mt = 0; mt < 2; ++mt) {
        int r0 = fr + mt * 16 + g;
        uint32_t o0 = (uint32_t)(r0 * 32 + ((t ^ sw) << 2));
        uint32_t o2 = (uint32_t)(r0 * 32 + (((t + 4) ^ sw) << 2));
        ah[mt][0] = *(const uint32_t*)(pA + o0);
        ah[mt][1] = *(const uint32_t*)(pA + o0 + 256);
        ah[mt][2] = *(const uint32_t*)(pA + o2);
        ah[mt][3] = *(const uint32_t*)(pA + o2 + 256);
        al[mt][0] = *(const uint32_t*)(pA + 4096 + o0);
        al[mt][1] = *(const uint32_t*)(pA + 4096 + o0 + 256);
        al[mt][2] = *(const uint32_t*)(pA + 4096 + o2);
        al[mt][3] = *(const uint32_t*)(pA + 4096 + o2 + 256);
    }
#pragma unroll
    for (int nt = 0; nt < 4; ++nt) {
        int rb = nb + nt * 8 + g;
        uint32_t o0 = (uint32_t)(rb * 32 + ((t ^ sw) << 2));
        uint32_t o1 = (uint32_t)(rb * 32 + (((t + 4) ^ sw) << 2));
        bh[nt][0] = *(const uint32_t*)(pB + o0);
        bh[nt][1] = *(const uint32_t*)(pB + o1);
        bl[nt][0] = *(const uint32_t*)(pB + 2048 + o0);
        bl[nt][1] = *(const uint32_t*)(pB + 2048 + o1);
    }
#pragma unroll
    for (int mt = 0; mt < 2; ++mt)
#pragma unroll
        for (int nt = 0; nt < 4; ++nt) {
            imma(hh[mt][nt], ah[mt][0], ah[mt][1], ah[mt][2], ah[mt][3], bh[nt][0], bh[nt][1]);
            imma(md[mt][nt], ah[mt][0], ah[mt][1], ah[mt][2], ah[mt][3], bl[nt][0], bl[nt][1]);
            imma(md[mt][nt], al[mt][0], al[mt][1], al[mt][2], al[mt][3], bh[nt][0], bh[nt][1]);
        }
}

__device__ __forceinline__ void stage_D(float* st, int hh[2][4][4], int md[2][4][4],
                                        float c1, float c2, int wid, int lane) {
    const int g = lane >> 2, t = lane & 3;
    const int fr = (wid >> 1) * 32, nb = (wid & 1) * 32;
#pragma unroll
    for (int mt = 0; mt < 2; ++mt)
#pragma unroll
        for (int nt = 0; nt < 4; ++nt) {
            int f0 = fr + mt * 16 + g, b0 = nb + nt * 8 + 2 * t;
            st[b0 * 132 + f0]           = (float)hh[mt][nt][0] * c1 + (float)md[mt][nt][0] * c2;
            st[(b0 + 1) * 132 + f0]     = (float)hh[mt][nt][1] * c1 + (float)md[mt][nt][1] * c2;
            st[b0 * 132 + f0 + 8]       = (float)hh[mt][nt][2] * c1 + (float)md[mt][nt][2] * c2;
            st[(b0 + 1) * 132 + f0 + 8] = (float)hh[mt][nt][3] * c1 + (float)md[mt][nt][3] * c2;
        }
}

#define ZACC()                                           \
    do {                                                 \
        _Pragma("unroll") for (int a_ = 0; a_ < 2; ++a_) \
        _Pragma("unroll") for (int b_ = 0; b_ < 4; ++b_) \
        _Pragma("unroll") for (int c_ = 0; c_ < 4; ++c_) \
        { hh[a_][b_][c_] = 0; md[a_][b_][c_] = 0; }      \
    } while (0)

// ---------------- main persistent kernel (120 CTAs) ----------------
__global__ void __launch_bounds__(256, 1) k_main(const float* __restrict__ b_h,
                                                 const float* __restrict__ bL,
                                                 float* __restrict__ out, int out_size) {
    extern __shared__ __align__(16) char smem[];
    const int tid = threadIdx.x;
    const int wid = tid >> 5, lane = tid & 31;
    const uint32_t sbase = smem_u32(smem);
    const int bid = blockIdx.x;
    const bool want_hf = (out_size >= (int)((size_t)S_ * BH_ + LBH_));
    int hh[2][4][4], md[2][4][4];

    // ---- phase A: P = X @ W_xh + b_h ----
    {
        const int m = bid & 7, srow = bid >> 3;   // m-tile, s-stripe
        const char* wb = g_Wq + (size_t)(1280 + m * 8) * 8192;
#pragma unroll
        for (int i = 0; i < 16; ++i)
            cp16(sbase + tid * 16 + i * 4096, wb + tid * 16 + i * 4096);
        cp_commit(); cp_wait0();
        __syncthreads();
        for (int s = srow; s < S_; s += 15) {
            const char* xb = g_Xq + (size_t)s * 32768;
#pragma unroll
            for (int i = 0; i < 8; ++i)
                cp16(sbase + 65536 + tid * 16 + i * 4096, xb + tid * 16 + i * 4096);
            cp_commit(); cp_wait0();
            __syncthreads();
            ZACC();
#pragma unroll
            for (int c = 0; c < 8; ++c)
                sub_i8(smem + c * 8192, smem + 65536 + c * 4096, wid, lane, hh, md);
            __syncthreads();
            stage_D((float*)(smem + 65536), hh, md, C1_A, C2_A, wid, lane);
            __syncthreads();
            {
                int b = tid >> 2, seg = tid & 3;
                float* Ps = g_P + (size_t)s * BH_ + (size_t)b * H_ + m * 128;
                const float* st = (const float*)(smem + 65536);
#pragma unroll
                for (int i = 0; i < 8; ++i) {
                    int ff = (seg + 4 * i) * 4;
                    float4 v = *(const float4*)(st + b * 132 + ff);
                    float4 bb = *(const float4*)(b_h + m * 128 + ff);
                    v.x += bb.x; v.y += bb.y; v.z += bb.z; v.w += bb.w;
                    *(float4*)(Ps + ff) = v;
                }
            }
            __syncthreads();
        }
    }
    grid_sync(NB);

    // ---- phase B setup (identical partition to R10) ----
    const int unit = bid / 3, ks = bid - unit * 3;
    const int gmat = unit >> 3, m = unit & 7;
    const int layer = (gmat == 0) ? 0 : ((gmat <= 2) ? 1 : 2);
    const int srcL = (gmat == 0) ? 0 : (gmat == 1) ? 1 : (gmat == 2) ? 0 : (gmat == 3) ? 2 : 1;
    const int c0 = ks * 11, c1 = (ks == 2) ? 32 : c0 + 11;
    const int nch = c1 - c0;
    const int tile = layer * 8 + m;
    const int gs = layer ? 6 : 3;
    const int rank = ks + ((layer && (gmat == 2 || gmat == 4)) ? 3 : 0);
    const int r0 = (64 * rank) / gs, r1 = (64 * (rank + 1)) / gs;
    const int f = tid & 127, mf = m * 128 + f;
    const float bias = layer ? bL[(layer - 1) * H_ + mf] : 0.0f;

    // resident weight slice (nch blocks x 8KB)
    {
        const char* wb = g_Wq + ((size_t)(gmat * 8 + m) * 32 + c0) * 8192;
        for (int c = 0; c < nch; ++c) {
            cp16(sbase + c * 8192 + tid * 16, wb + (size_t)c * 8192 + tid * 16);
            cp16(sbase + c * 8192 + 4096 + tid * 16, wb + (size_t)c * 8192 + 4096 + tid * 16);
        }
        cp_commit(); cp_wait0();
        __syncthreads();
    }

    for (int s = 0; s < S_; ++s) {
        if (tid == 0) {
            spin_ge(&g_hready[srcL * 32], (unsigned)c_inc[srcL] * (unsigned)s);
            __threadfence();
        }
        __syncthreads();
        const char* hb = g_hq + (size_t)(s & 1) * 393216 + (size_t)srcL * 131072 + (size_t)c0 * 4096;
        // pipelined B load: block c computed while c+1/c+2 stream in
        cp16(sbase + BOFF + tid * 16, hb + tid * 16);
        cp_commit();
        if (nch > 1) cp16(sbase + BOFF + 4096 + tid * 16, hb + 4096 + tid * 16);
        cp_commit();
        ZACC();
        for (int c = 0; c < nch; ++c) {
            if (c + 2 < nch)
                cp16(sbase + BOFF + (c + 2) * 4096 + tid * 16, hb + (size_t)(c + 2) * 4096 + tid * 16);
            cp_commit();
            cp_wait2();
            __syncthreads();
            sub_i8(smem + c * 8192, smem + BOFF + c * 4096, wid, lane, hh, md);
        }
        if (tid == 0) { __threadfence(); atomicAdd(&g_hused[srcL * 32], 1u); }
        __syncthreads();
        stage_D((float*)(smem + BOFF), hh, md, C1_REC, C2_REC, wid, lane);
        __syncthreads();

        float* pbase = g_part + (size_t)(s & 1) * NB * 8192;
        {
            int b = tid >> 2, seg = tid & 3;
            float* pp = pbase + (size_t)bid * 8192 + b * 128;
            const float* st = (const float*)(smem + BOFF);
#pragma unroll
            for (int i = 0; i < 8; ++i) {
                int ff = (seg + 4 * i) * 4;
                *(float4*)(pp + ff) = *(const float4*)(st + b * 132 + ff);
            }
        }
        __threadfence();
        __syncthreads();
        if (tid == 0) {
            atomicAdd(&g_pdone[tile * 32], 1u);
            spin_ge(&g_pdone[tile * 32], (unsigned)gs * (unsigned)(s + 1));
            spin_ge(&g_hused[layer * 32], (unsigned)c_cons[layer] * (unsigned)s);
            __threadfence();
        }
        __syncthreads();

        // epilogue: combine partials, tanh, write h (2-plane int8) + out
        {
            const float* pa = pbase + (size_t)(((layer == 0 ? 0 : (layer == 1 ? 1 : 3)) * 8 + m) * 3) * 8192;
            const float* pb2 = pbase + (size_t)(((layer == 1 ? 2 : 4) * 8 + m) * 3) * 8192;
            char* dsth = g_hq + (size_t)((s & 1) ^ 1) * 393216 +
                         ((size_t)layer * 32 + (mf >> 5)) * 4096;
            const int kk = mf & 31;
            float* os = out + (size_t)s * BH_;
            for (int b = r0 + (tid >> 7); b < r1; b += 2) {
                int idx = b * 128 + f;
                float v = bias + pa[idx] + pa[8192 + idx] + pa[16384 + idx];
                if (layer) v += pb2[idx] + pb2[8192 + idx] + pb2[16384 + idx];
                else       v += g_P[(size_t)s * BH_ + (size_t)b * H_ + mf];
                float o = tanhf(v);
                float sv = o * 127.0f;
                int p = __float2int_rn(sv);
                int q = __float2int_rn((sv - (float)p) * 254.0f);
                uint32_t oo = rowoff8(b, kk);
                dsth[oo] = (char)p;
                dsth[2048 + oo] = (char)q;
                if (layer == 2) os[(size_t)b * H_ + mf] = o;
                if (s == S_ - 1 && want_hf)
                    out[(size_t)S_ * BH_ + (size_t)layer * BH_ + (size_t)b * H_ + mf] = o;
            }
        }
        __threadfence();
        __syncthreads();
        if (tid == 0) atomicAdd(&g_hready[layer * 32], 1u);
    }
}

extern "C" void kernel_launch(void* const* d_in, const int* in_sizes, int n_in,
                              void* d_out, int out_size) {
    const float* X    = (const float*)d_in[0];
    const float* W_xh = (const float*)d_in[1];
    const float* W_hh = (const float*)d_in[2];
    const float* b_h  = (const float*)d_in[3];
    const float* W_l  = (const float*)d_in[4];
    const float* U_l  = (const float*)d_in[5];
    const float* b_l  = (const float*)d_in[6];
    float* out = (float*)d_out;

    cudaFuncSetAttribute(k_main, cudaFuncAttributeMaxDynamicSharedMemorySize, SMEM_DYN);
    k_init<<<768, 256>>>();
    k_prepw<<<20480, 256>>>(W_hh, W_l, U_l);
    k_prepxh<<<1024, 256>>>(W_xh);
    k_prepx<<<32768, 256>>>(X);
    k_main<<<NB, 256, SMEM_DYN>>>(b_h, b_l, out, out_size);
}

// round 17
// speedup vs baseline: 1.8208x; 1.8208x over previous
#include <cuda_runtime.h>
#include <cuda_fp16.h>
#include <math.h>
#include <stdint.h>

#define S_ 512
#define B_ 64
#define I_ 256
#define H_ 1024
#define BH_ 65536
#define LBH_ 196608
#define NB 120
#define SLOT 20480          // phase-A pipeline slot
#define BOFF 180224         // phase-B: B region / stage scratch
#define SMEM_DYN 225280
#define LOSCALE 2048.0f
#define ILOSCALE (1.0f / 2048.0f)

// ---------------- static device scratch ----------------
__device__ __align__(16) float g_P[(size_t)S_ * BH_];
__device__ __align__(16) __half g_Whi[2688 * 2048];   // 5 mats + Wxh, blocked K16 x 8 mtiles
__device__ __align__(16) __half g_Wlo[2688 * 2048];   // lo plane, pre-scaled by 2^11
__device__ __align__(16) __half g_Xf[8192 * 1024];    // X fp16, blocked
__device__ __align__(16) __half g_hf[2 * LBH_];       // h fp16, double-buffered
__device__ __align__(16) float g_part[2 * NB * 8192]; // partials, parity double-buffered
__device__ unsigned g_pdone[24 * 32];
__device__ unsigned g_hready[3 * 32];
__device__ unsigned g_hused[3 * 32];
__device__ unsigned g_cnt;
__device__ volatile unsigned g_gen;

__constant__ int c_inc[3]  = {24, 48, 48};
__constant__ int c_cons[3] = {48, 48, 24};

__device__ __forceinline__ uint32_t rowoff(int r, int j) {
    int w = j >> 1;
    return (uint32_t)(r * 16 + (((w ^ (r & 4)) << 1) | (j & 1)));
}

// ---------------- PTX helpers ----------------
__device__ __forceinline__ uint32_t smem_u32(const void* p) {
    uint32_t a;
    asm("{ .reg .u64 t; cvta.to.shared.u64 t, %1; cvt.u32.u64 %0, t; }" : "=r"(a) : "l"(p));
    return a;
}
__device__ __forceinline__ void cp16(uint32_t s, const void* g) {
    asm volatile("cp.async.cg.shared.global [%0], [%1], 16;" :: "r"(s), "l"(g) : "memory");
}
__device__ __forceinline__ void cp_commit() { asm volatile("cp.async.commit_group;" ::: "memory"); }
__device__ __forceinline__ void cp_wait2()  { asm volatile("cp.async.wait_group 2;" ::: "memory"); }
__device__ __forceinline__ void cp_wait0()  { asm volatile("cp.async.wait_group 0;" ::: "memory"); }

// fp32-accumulator HMMA (hi plane)
__device__ __forceinline__ void mmaf16(float* d, uint32_t a0, uint32_t a1, uint32_t a2,
                                       uint32_t a3, uint32_t b0, uint32_t b1) {
    asm volatile(
        "mma.sync.aligned.m16n8k16.row.col.f32.f16.f16.f32 "
        "{%0,%1,%2,%3}, {%4,%5,%6,%7}, {%8,%9}, {%0,%1,%2,%3};"
        : "+f"(d[0]), "+f"(d[1]), "+f"(d[2]), "+f"(d[3])
        : "r"(a0), "r"(a1), "r"(a2), "r"(a3), "r"(b0), "r"(b1));
}
// fp16-accumulator HMMA (lo plane; D/C packed f16x2 pairs)
__device__ __forceinline__ void mmaf16acc(uint32_t* d, uint32_t a0, uint32_t a1, uint32_t a2,
                                          uint32_t a3, uint32_t b0, uint32_t b1) {
    asm volatile(
        "mma.sync.aligned.m16n8k16.row.col.f16.f16.f16.f16 "
        "{%0,%1}, {%2,%3,%4,%5}, {%6,%7}, {%0,%1};"
        : "+r"(d[0]), "+r"(d[1])
        : "r"(a0), "r"(a1), "r"(a2), "r"(a3), "r"(b0), "r"(b1));
}

__device__ __forceinline__ void grid_sync(unsigned nb) {
    __syncthreads();
    if (threadIdx.x == 0) {
        __threadfence();
        unsigned g = g_gen;
        if (atomicAdd(&g_cnt, 1u) == nb - 1u) {
            g_cnt = 0;
            __threadfence();
            g_gen = g + 1u;
        } else {
            while (g_gen == g) { }
        }
    }
    __syncthreads();
}
__device__ __forceinline__ void spin_ge(unsigned* ctr, unsigned tgt) {
    while (*(volatile unsigned*)ctr < tgt) { }
}

// ---------------- prep kernels ----------------
__global__ void k_init() {
    int i = blockIdx.x * blockDim.x + threadIdx.x;
    uint32_t* a = (uint32_t*)g_hf;
    if (i < 196608) a[i] = 0u;
    if (i < 24 * 32) g_pdone[i] = 0u;
    if (i < 3 * 32) { g_hready[i] = 0u; g_hused[i] = 0u; }
}
__device__ __forceinline__ void wsplit(float v, size_t e) {
    __half hi = __float2half(v);
    g_Whi[e] = hi;
    g_Wlo[e] = __float2half((v - __half2float(hi)) * LOSCALE);
}
__global__ void k_prepw(const float* __restrict__ Whh, const float* __restrict__ Wl,
                        const float* __restrict__ Ul) {
    int idx = blockIdx.x * blockDim.x + threadIdx.x;
    if (idx >= 5 * 1024 * 1024) return;
    int g = idx >> 20, rem = idx & 1048575, k = rem >> 10, f = rem & 1023;
    float v;
    if (g == 0)      v = Whh[(size_t)k * H_ + f];
    else if (g == 1) v = Ul[(size_t)k * H_ + f];
    else if (g == 2) v = Wl[(size_t)k * H_ + f];
    else if (g == 3) v = Ul[(size_t)H_ * H_ + (size_t)k * H_ + f];
    else             v = Wl[(size_t)H_ * H_ + (size_t)k * H_ + f];
    size_t blk = (size_t)(g * 8 + (f >> 7)) * 64 + (k >> 4);
    wsplit(v, blk * 2048 + rowoff(f & 127, k & 15));
}
__global__ void k_prepxh(const float* __restrict__ Wxh) {
    int idx = blockIdx.x * blockDim.x + threadIdx.x;
    if (idx >= 256 * 1024) return;
    int k = idx >> 10, f = idx & 1023;
    size_t blk = 2560 + (size_t)(f >> 7) * 16 + (k >> 4);
    wsplit(Wxh[(size_t)k * H_ + f], blk * 2048 + rowoff(f & 127, k & 15));
}
__global__ void k_prepx(const float* __restrict__ X) {
    int idx = blockIdx.x * blockDim.x + threadIdx.x;
    if (idx >= S_ * B_ * I_) return;
    int s = idx >> 14, b = (idx >> 8) & 63, i = idx & 255;
    g_Xf[((size_t)s * 16 + (i >> 4)) * 1024 + rowoff(b, i & 15)] = __float2half(X[idx]);
}

// ---------------- GEMM core ----------------
// hi plane -> fp32 accum dh; lo plane -> fp16 accum ll (packed f16x2 x2 regs)
__device__ __forceinline__ void sub_iter(const char* Ah, const char* Al, const char* Bf,
                                         int wid, int lane,
                                         float dh[2][4][4], uint32_t ll[2][4][2]) {
    const int g = lane >> 2, t = lane & 3;
    const int fr = (wid >> 1) * 32, nb = (wid & 1) * 32;
    const int sw = g & 4;
    uint32_t ah[2][4], al[2][4], bb[4][2];
#pragma unroll
    for (int mt = 0; mt < 2; ++mt) {
        int r0 = fr + mt * 16 + g;
        uint32_t o0 = (uint32_t)(r0 * 32 + ((t ^ sw) << 2));
        uint32_t o2 = (uint32_t)(r0 * 32 + (((t + 4) ^ sw) << 2));
        ah[mt][0] = *(const uint32_t*)(Ah + o0);
        ah[mt][1] = *(const uint32_t*)(Ah + o0 + 256);
        ah[mt][2] = *(const uint32_t*)(Ah + o2);
        ah[mt][3] = *(const uint32_t*)(Ah + o2 + 256);
        al[mt][0] = *(const uint32_t*)(Al + o0);
        al[mt][1] = *(const uint32_t*)(Al + o0 + 256);
        al[mt][2] = *(const uint32_t*)(Al + o2);
        al[mt][3] = *(const uint32_t*)(Al + o2 + 256);
    }
#pragma unroll
    for (int nt = 0; nt < 4; ++nt) {
        int rb = nb + nt * 8 + g;
        uint32_t o0 = (uint32_t)(rb * 32 + ((t ^ sw) << 2));
        uint32_t o1 = (uint32_t)(rb * 32 + (((t + 4) ^ sw) << 2));
        bb[nt][0] = *(const uint32_t*)(Bf + o0);
        bb[nt][1] = *(const uint32_t*)(Bf + o1);
    }
#pragma unroll
    for (int mt = 0; mt < 2; ++mt)
#pragma unroll
        for (int nt = 0; nt < 4; ++nt) {
            mmaf16(dh[mt][nt], ah[mt][0], ah[mt][1], ah[mt][2], ah[mt][3], bb[nt][0], bb[nt][1]);
            mmaf16acc(ll[mt][nt], al[mt][0], al[mt][1], al[mt][2], al[mt][3], bb[nt][0], bb[nt][1]);
        }
}

// phase-A streaming pipeline
__device__ __forceinline__ void load_chunkA(uint32_t so, const char* Ah, const char* Al,
                                            const char* Bf, int c, int tid) {
    size_t ao = (size_t)c * 8192 + tid * 16;
    cp16(so + tid * 16, Ah + ao);
    cp16(so + 4096 + tid * 16, Ah + ao + 4096);
    cp16(so + 8192 + tid * 16, Al + ao);
    cp16(so + 12288 + tid * 16, Al + ao + 4096);
    cp16(so + 16384 + tid * 16, Bf + (size_t)c * 4096 + tid * 16);
}
__device__ __forceinline__ void gemm_pipeA(const char* Ah, const char* Al, const char* Bf,
                                           const char* sm, uint32_t sbase,
                                           float dh[2][4][4], uint32_t ll[2][4][2],
                                           int tid, int wid, int lane) {
#pragma unroll
    for (int i = 0; i < 3; ++i) {
        load_chunkA(sbase + i * SLOT, Ah, Al, Bf, i, tid);
        cp_commit();
    }
    for (int c = 0; c < 8; ++c) {
        const int slot = c & 3;
        cp_wait2();
        __syncthreads();
        if (c + 3 < 8) load_chunkA(sbase + ((c + 3) & 3) * SLOT, Ah, Al, Bf, c + 3, tid);
        cp_commit();
        const char* p = sm + slot * SLOT;
        sub_iter(p, p + 8192, p + 16384, wid, lane, dh, ll);
        sub_iter(p + 4096, p + 12288, p + 18432, wid, lane, dh, ll);
    }
    cp_wait0();
    __syncthreads();
}

__device__ __forceinline__ void stage_D(float* st, float dh[2][4][4], uint32_t ll[2][4][2],
                                        int wid, int lane) {
    const int g = lane >> 2, t = lane & 3;
    const int fr = (wid >> 1) * 32, nb = (wid & 1) * 32;
#pragma unroll
    for (int mt = 0; mt < 2; ++mt)
#pragma unroll
        for (int nt = 0; nt < 4; ++nt) {
            int f0 = fr + mt * 16 + g, b0 = nb + nt * 8 + 2 * t;
            float2 l0 = __half22float2(*(const __half2*)&ll[mt][nt][0]);
            float2 l1 = __half22float2(*(const __half2*)&ll[mt][nt][1]);
            st[b0 * 132 + f0]           = dh[mt][nt][0] + l0.x * ILOSCALE;
            st[(b0 + 1) * 132 + f0]     = dh[mt][nt][1] + l0.y * ILOSCALE;
            st[b0 * 132 + f0 + 8]       = dh[mt][nt][2] + l1.x * ILOSCALE;
            st[(b0 + 1) * 132 + f0 + 8] = dh[mt][nt][3] + l1.y * ILOSCALE;
        }
}

#define ZACC()                                           \
    do {                                                 \
        _Pragma("unroll") for (int a_ = 0; a_ < 2; ++a_) \
        _Pragma("unroll") for (int b_ = 0; b_ < 4; ++b_) \
        {                                                \
            _Pragma("unroll") for (int c_ = 0; c_ < 4; ++c_) dh[a_][b_][c_] = 0.0f; \
            ll[a_][b_][0] = 0u; ll[a_][b_][1] = 0u;      \
        }                                                \
    } while (0)

// ---------------- main persistent kernel (120 CTAs, dataflow-synced) ----------------
__global__ void __launch_bounds__(256, 1) k_main(const float* __restrict__ b_h,
                                                 const float* __restrict__ bL,
                                                 float* __restrict__ out, int out_size) {
    extern __shared__ __align__(16) char smem[];
    const int tid = threadIdx.x;
    const int wid = tid >> 5, lane = tid & 31;
    const uint32_t sbase = smem_u32(smem);
    const int bid = blockIdx.x;
    const bool want_hf = (out_size >= (int)((size_t)S_ * BH_ + LBH_));
    float dh[2][4][4];
    uint32_t ll[2][4][2];

    // ---- phase A: P = X @ W_xh + b_h ----
    for (int u = bid; u < 4096; u += NB) {
        int s = u >> 3, m = u & 7;
        ZACC();
        const char* Ah = (const char*)g_Whi + ((size_t)2560 + m * 16) * 4096;
        const char* Al = (const char*)g_Wlo + ((size_t)2560 + m * 16) * 4096;
        const char* Bf = (const char*)g_Xf + (size_t)s * 16 * 2048;
        gemm_pipeA(Ah, Al, Bf, smem, sbase, dh, ll, tid, wid, lane);
        stage_D((float*)smem, dh, ll, wid, lane);
        __syncthreads();
        {
            int b = tid >> 2, seg = tid & 3;
            float* Ps = g_P + (size_t)s * BH_ + (size_t)b * H_ + m * 128;
            const float* st = (const float*)smem;
#pragma unroll
            for (int i = 0; i < 8; ++i) {
                int ff = (seg + 4 * i) * 4;
                float4 v = *(const float4*)(st + b * 132 + ff);
                float4 bb = *(const float4*)(b_h + m * 128 + ff);
                v.x += bb.x; v.y += bb.y; v.z += bb.z; v.w += bb.w;
                *(float4*)(Ps + ff) = v;
            }
        }
        __syncthreads();
    }
    grid_sync(NB);

    // ---- phase B setup ----
    const int unit = bid / 3, ks = bid - unit * 3;
    const int gmat = unit >> 3, m = unit & 7;
    const int layer = (gmat == 0) ? 0 : ((gmat <= 2) ? 1 : 2);
    const int srcL = (gmat == 0) ? 0 : (gmat == 1) ? 1 : (gmat == 2) ? 0 : (gmat == 3) ? 2 : 1;
    const int c0 = ks * 11, c1 = (ks == 2) ? 32 : c0 + 11;
    const int nch = c1 - c0;
    const int tile = layer * 8 + m;
    const int gs = layer ? 6 : 3;
    const int rank = ks + ((layer && (gmat == 2 || gmat == 4)) ? 3 : 0);
    const int r0 = (64 * rank) / gs, r1 = (64 * (rank + 1)) / gs;
    const int f = tid & 127, mf = m * 128 + f;
    const float bias = layer ? bL[(layer - 1) * H_ + mf] : 0.0f;

    // load resident weight slice into SMEM (once)
    {
        const char* gh = (const char*)g_Whi + (size_t)(gmat * 8 + m) * 64 * 4096;
        const char* gl = (const char*)g_Wlo + (size_t)(gmat * 8 + m) * 64 * 4096;
        for (int c = 0; c < nch; ++c) {
            size_t gg = (size_t)(c0 + c) * 8192 + tid * 16;
            uint32_t so = sbase + c * 16384 + tid * 16;
            cp16(so, gh + gg);
            cp16(so + 4096, gh + gg + 4096);
            cp16(so + 8192, gl + gg);
            cp16(so + 12288, gl + gg + 4096);
        }
        cp_commit();
        cp_wait0();
        __syncthreads();
    }

    // ---- phase B: recurrence ----
    for (int s = 0; s < S_; ++s) {
        if (tid == 0) {
            spin_ge(&g_hready[srcL * 32], (unsigned)c_inc[srcL] * (unsigned)s);
            __threadfence();
        }
        __syncthreads();
        const char* hb = (const char*)(g_hf + (size_t)(s & 1) * LBH_ + (size_t)srcL * 65536)
                         + (size_t)c0 * 4096;
        // pipelined B load: chunk c computes while c+1/c+2 stream in
        cp16(sbase + BOFF + tid * 16, hb + tid * 16);
        cp_commit();
        cp16(sbase + BOFF + 4096 + tid * 16, hb + 4096 + tid * 16);
        cp_commit();
        ZACC();
        for (int c = 0; c < nch; ++c) {
            if (c + 2 < nch)
                cp16(sbase + BOFF + (c + 2) * 4096 + tid * 16, hb + (size_t)(c + 2) * 4096 + tid * 16);
            cp_commit();
            cp_wait2();
            __syncthreads();
            const char* pA = smem + c * 16384;
            const char* pB = smem + BOFF + c * 4096;
            sub_iter(pA, pA + 8192, pB, wid, lane, dh, ll);
            sub_iter(pA + 4096, pA + 12288, pB + 2048, wid, lane, dh, ll);
        }
        if (tid == 0) { __threadfence(); atomicAdd(&g_hused[srcL * 32], 1u); }
        __syncthreads();                 // B region dead; reuse as stage scratch
        stage_D((float*)(smem + BOFF), dh, ll, wid, lane);
        __syncthreads();

        float* pbase = g_part + (size_t)(s & 1) * NB * 8192;
        {
            int b = tid >> 2, seg = tid & 3;
            float* pp = pbase + (size_t)bid * 8192 + b * 128;
            const float* st = (const float*)(smem + BOFF);
#pragma unroll
            for (int i = 0; i < 8; ++i) {
                int ff = (seg + 4 * i) * 4;
                *(float4*)(pp + ff) = *(const float4*)(st + b * 132 + ff);
            }
        }
        __threadfence();
        __syncthreads();
        if (tid == 0) {
            atomicAdd(&g_pdone[tile * 32], 1u);
            spin_ge(&g_pdone[tile * 32], (unsigned)gs * (unsigned)(s + 1));
            spin_ge(&g_hused[layer * 32], (unsigned)c_cons[layer] * (unsigned)s);
            __threadfence();
        }
        __syncthreads();

        // epilogue: combine partials, tanh, write h(+out), signal hready
        {
            const float* pa = pbase + (size_t)(((layer == 0 ? 0 : (layer == 1 ? 1 : 3)) * 8 + m) * 3) * 8192;
            const float* pb2 = pbase + (size_t)(((layer == 1 ? 2 : 4) * 8 + m) * 3) * 8192;
            const size_t wrE = (size_t)((s & 1) ^ 1) * LBH_;
            __half* dst = g_hf + wrE + ((size_t)layer * 64 + (mf >> 4)) * 1024;
            float* os = out + (size_t)s * BH_;
            for (int b = r0 + (tid >> 7); b < r1; b += 2) {
                int idx = b * 128 + f;
                float v = bias + pa[idx] + pa[8192 + idx] + pa[16384 + idx];
                if (layer) v += pb2[idx] + pb2[8192 + idx] + pb2[16384 + idx];
                else       v += g_P[(size_t)s * BH_ + (size_t)b * H_ + mf];
                float o = tanhf(v);
                dst[rowoff(b, mf & 15)] = __float2half(o);
                if (layer == 2) os[(size_t)b * H_ + mf] = o;
                if (s == S_ - 1 && want_hf)
                    out[(size_t)S_ * BH_ + (size_t)layer * BH_ + (size_t)b * H_ + mf] = o;
            }
        }
        __threadfence();
        __syncthreads();
        if (tid == 0) atomicAdd(&g_hready[layer * 32], 1u);
    }
}

extern "C" void kernel_launch(void* const* d_in, const int* in_sizes, int n_in,
                              void* d_out, int out_size) {
    const float* X    = (const float*)d_in[0];
    const float* W_xh = (const float*)d_in[1];
    const float* W_hh = (const float*)d_in[2];
    const float* b_h  = (const float*)d_in[3];
    const float* W_l  = (const float*)d_in[4];
    const float* U_l  = (const float*)d_in[5];
    const float* b_l  = (const float*)d_in[6];
    float* out = (float*)d_out;

    cudaFuncSetAttribute(k_main, cudaFuncAttributeMaxDynamicSharedMemorySize, SMEM_DYN);
    k_init<<<768, 256>>>();
    k_prepw<<<20480, 256>>>(W_hh, W_l, U_l);
    k_prepxh<<<1024, 256>>>(W_xh);
    k_prepx<<<32768, 256>>>(X);
    k_main<<<NB, 256, SMEM_DYN>>>(b_h, b_l, out, out_size);
}